// round 13
// baseline (speedup 1.0000x reference)
#include <cuda_runtime.h>
#include <cstdint>

#define BS   4
#define SEQ  128
#define DIM  768
#define HID  768
#define NOUT 2
#define MROWS (BS * SEQ)                    // 512
#define KSPLIT 384                          // K per split-K half

// ---------------- device scratch (no allocation allowed) -------------------
__device__ float g_ha[MROWS * HID];         // a @ W1[:D]          (RED-merged)
__device__ float g_hb[MROWS * HID];         // b @ W1[D:] + b1     (RED-merged)

// ---------------------------------------------------------------------------
__device__ __forceinline__ uint32_t smem_u32(const void* p) {
    uint32_t a;
    asm("{ .reg .u64 t; cvta.to.shared.u64 t, %1; cvt.u32.u64 %0, t; }"
        : "=r"(a) : "l"(p));
    return a;
}

__device__ __forceinline__ void cp_async16(uint32_t saddr, const void* gptr) {
    asm volatile("cp.async.cg.shared.global [%0], [%1], 16;"
                 :: "r"(saddr), "l"(gptr) : "memory");
}
__device__ __forceinline__ void cp_commit() {
    asm volatile("cp.async.commit_group;" ::: "memory");
}
template <int N>
__device__ __forceinline__ void cp_wait() {
    asm volatile("cp.async.wait_group %0;" :: "n"(N) : "memory");
}

__device__ __forceinline__ uint32_t f2tf32(float x) {
    uint32_t u;
    asm("cvt.rna.tf32.f32 %0, %1;" : "=r"(u) : "f"(x));
    return u;
}

__device__ __forceinline__ void ldsm_x4(uint32_t* d, uint32_t saddr) {
    asm volatile(
        "ldmatrix.sync.aligned.m8n8.x4.shared.b16 {%0,%1,%2,%3}, [%4];"
        : "=r"(d[0]), "=r"(d[1]), "=r"(d[2]), "=r"(d[3]) : "r"(saddr));
}

__device__ __forceinline__ void mma_tf32(float* c, const uint32_t* a,
                                         const uint32_t* b) {
    asm volatile(
        "mma.sync.aligned.m16n8k8.row.col.f32.tf32.tf32.f32 "
        "{%0,%1,%2,%3}, {%4,%5,%6,%7}, {%8,%9}, {%0,%1,%2,%3};"
        : "+f"(c[0]), "+f"(c[1]), "+f"(c[2]), "+f"(c[3])
        : "r"(a[0]), "r"(a[1]), "r"(a[2]), "r"(a[3]), "r"(b[0]), "r"(b[1]));
}

// ---------------------------------------------------------------------------
// Kernel 1: projection GEMM (structure unchanged — proven).
// Split-K=2 now merges via RED.F32 into zeroed g_ha/g_hb (commutative
// two-term fp add -> bit-deterministic).
// ---------------------------------------------------------------------------
#define ALD 36
#define BLD 72
#define STG_A (64 * ALD)
#define STG_B (32 * BLD)
#define PROJ_SMEM_BYTES (3 * (STG_A + STG_B) * 4)   // 55296

__global__ __launch_bounds__(128) void proj_tc(
    const float* __restrict__ a, const float* __restrict__ b,
    const float* __restrict__ W1, const float* __restrict__ b1)
{
    extern __shared__ float psm[];
    float* const Asm = psm;
    float* const Bsm = psm + 3 * STG_A;

    const int tid = threadIdx.x;
    const int wid = tid >> 5;
    const int lane = tid & 31;
    const int r = lane >> 2;
    const int c = lane & 3;
    const int wm = (wid >> 1) * 32;
    const int wn = (wid & 1) * 32;

    const int n0 = blockIdx.x * 64;
    const int m0 = blockIdx.y * 64;
    const int z  = blockIdx.z & 1;
    const int kh = blockIdx.z >> 1;
    const int kbase = kh * KSPLIT;

    const float* __restrict__ X = z ? b : a;
    const float* __restrict__ W = W1 + (size_t)z * DIM * HID;

    const uint32_t sA = smem_u32(Asm);
    const uint32_t sB = smem_u32(Bsm);

    const uint32_t a_lm0 =
        (uint32_t)(((wm + (lane & 7) + ((lane >> 3) & 1) * 8) * ALD
                    + ((lane >> 4) & 1) * 4) * 4);

    auto ldchunk = [&](int chunk, int s) {
        const int k0 = kbase + chunk * 32;
        #pragma unroll
        for (int i = 0; i < 4; i++) {
            int f = i * 128 + tid;
            int row = f >> 3, kc = (f & 7) * 4;
            cp_async16(sA + (uint32_t)(s * STG_A + row * ALD + kc) * 4,
                       X + (size_t)(m0 + row) * DIM + k0 + kc);
        }
        #pragma unroll
        for (int i = 0; i < 4; i++) {
            int f = i * 128 + tid;
            int kr = f >> 4, nc = (f & 15) * 4;
            cp_async16(sB + (uint32_t)(s * STG_B + kr * BLD + nc) * 4,
                       W + (size_t)(k0 + kr) * HID + n0 + nc);
        }
        cp_commit();
    };

    float acc[2][4][4] = {};

    ldchunk(0, 0);
    ldchunk(1, 1);

    for (int chunk = 0; chunk < 12; chunk++) {
        const int s = chunk % 3;
        if (chunk < 11) cp_wait<1>(); else cp_wait<0>();
        __syncthreads();

        if (chunk + 2 < 12) ldchunk(chunk + 2, (chunk + 2) % 3);

        const uint32_t aStage = sA + (uint32_t)(s * STG_A) * 4;
        const float* Bb = Bsm + s * STG_B;
        #pragma unroll
        for (int ks = 0; ks < 4; ks++) {
            const int kb = ks * 8;
            uint32_t af[2][4];
            #pragma unroll
            for (int mt = 0; mt < 2; mt++) {
                ldsm_x4(af[mt], aStage + a_lm0
                                + (uint32_t)(mt * 16 * ALD + kb) * 4);
                af[mt][0] = f2tf32(__uint_as_float(af[mt][0]));
                af[mt][1] = f2tf32(__uint_as_float(af[mt][1]));
                af[mt][2] = f2tf32(__uint_as_float(af[mt][2]));
                af[mt][3] = f2tf32(__uint_as_float(af[mt][3]));
            }
            uint32_t bf[4][2];
            #pragma unroll
            for (int nt = 0; nt < 4; nt++) {
                const float* bp = Bb + (kb + c) * BLD + wn + nt * 8 + r;
                bf[nt][0] = f2tf32(bp[0]);
                bf[nt][1] = f2tf32(bp[4 * BLD]);
            }
            #pragma unroll
            for (int nt = 0; nt < 4; nt++)
                #pragma unroll
                for (int mt = 0; mt < 2; mt++)
                    mma_tf32(acc[mt][nt], af[mt], bf[nt]);
        }
    }

    // epilogue: RED.F32 merge of the two k-halves (+ b1 once on z=1 kh=0)
    float* __restrict__ outp = z ? g_hb : g_ha;
    const bool addb = (z == 1) && (kh == 0);
    #pragma unroll
    for (int mt = 0; mt < 2; mt++) {
        #pragma unroll
        for (int nt = 0; nt < 4; nt++) {
            int m = m0 + wm + mt * 16 + r;
            int n = n0 + wn + nt * 8 + c * 2;
            float v[4] = { acc[mt][nt][0], acc[mt][nt][1],
                           acc[mt][nt][2], acc[mt][nt][3] };
            if (addb) {
                float2 bb = *(const float2*)&b1[n];
                v[0] += bb.x; v[1] += bb.y; v[2] += bb.x; v[3] += bb.y;
            }
            float* p0 = &outp[(size_t)m * HID + n];
            float* p1 = &outp[(size_t)(m + 8) * HID + n];
            atomicAdd(p0, v[0]);     atomicAdd(p0 + 1, v[1]);
            atomicAdd(p1, v[2]);     atomicAdd(p1 + 1, v[3]);
        }
    }
}

// ---------------------------------------------------------------------------
// Kernel 2: pairwise relu + reduce to O=2 — low-reg all-resident version.
// Tile 16s x 16t, grid (8, 8, 4) = 256 CTAs, 256 threads (<=64 regs,
// 4 CTAs/SM ceiling -> whole grid resident). 4 h-groups of 64 threads
// (192 h each, 6 chunks of 32 h). Thread tile 2s x 2t. Per 4h: 6 LDS.128
// (all conflict-free/broadcast) feed 64 math ops. 2-step smem tree.
// ---------------------------------------------------------------------------
#define QLD 36
#define QA_G (16 * QLD)                      // 576 floats per group
#define QB_BASE (4 * QA_G)                   // 2304
#define QW_BASE (QB_BASE + 4 * QA_G)         // 4608
#define QW_G 72

__global__ __launch_bounds__(256, 4) void pair_kernel(
    const float* __restrict__ W2, const float* __restrict__ b2,
    float* __restrict__ out)
{
    __shared__ float sm[QW_BASE + 4 * QW_G];     // 19584 B

    const int tt = blockIdx.x;              // t tile (16)
    const int st = blockIdx.y;              // s tile (16)
    const int batch = blockIdx.z;

    const int tid = threadIdx.x;
    const int g  = tid >> 6;                // 0..3 h-group
    const int lt = tid & 63;
    const int sq = lt >> 3;                 // 0..7
    const int tq = lt & 7;                  // 0..7

    float* const sA = sm + g * QA_G;                 // [16][QLD]
    float* const sB = sm + QB_BASE + g * QA_G;       // [16][QLD]
    float* const sW = sm + QW_BASE + g * QW_G;       // [64]

    const float* __restrict__ hap =
        g_ha + (size_t)(batch * SEQ + st * 16) * HID;
    const float* __restrict__ hbp =
        g_hb + (size_t)(batch * SEQ + tt * 16) * HID;

    float acc[2][2][2] = {};                // [i(s)][j(t)][o]

    #pragma unroll 1
    for (int c = 0; c < 6; c++) {
        const int h0 = g * 192 + c * 32;

        // fills: 16 rows x 32 h = 128 f4 each; 2 f4 per thread (coalesced)
        #pragma unroll
        for (int q = 0; q < 2; q++) {
            int f = q * 64 + lt;
            int row = f >> 3, col = (f & 7) * 4;
            *(float4*)&sA[row * QLD + col] =
                *(const float4*)&hap[(size_t)row * HID + h0 + col];
            *(float4*)&sB[row * QLD + col] =
                *(const float4*)&hbp[(size_t)row * HID + h0 + col];
        }
        if (lt < 16)
            *(float4*)&sW[lt * 4] = *(const float4*)&W2[h0 * 2 + lt * 4];
        __syncthreads();

        #pragma unroll
        for (int hh = 0; hh < 32; hh += 4) {
            float4 A[2], B[2];
            A[0] = *(const float4*)&sA[sq * QLD + hh];
            A[1] = *(const float4*)&sA[(sq + 8) * QLD + hh];
            B[0] = *(const float4*)&sB[tq * QLD + hh];
            B[1] = *(const float4*)&sB[(tq + 8) * QLD + hh];
            float4 W0 = *(const float4*)&sW[2 * hh];
            float4 W1 = *(const float4*)&sW[2 * hh + 4];

            #pragma unroll
            for (int i = 0; i < 2; i++) {
                #pragma unroll
                for (int j = 0; j < 2; j++) {
                    float r;
                    r = fmaxf(A[i].x + B[j].x, 0.f);
                    acc[i][j][0] += r * W0.x; acc[i][j][1] += r * W0.y;
                    r = fmaxf(A[i].y + B[j].y, 0.f);
                    acc[i][j][0] += r * W0.z; acc[i][j][1] += r * W0.w;
                    r = fmaxf(A[i].z + B[j].z, 0.f);
                    acc[i][j][0] += r * W1.x; acc[i][j][1] += r * W1.y;
                    r = fmaxf(A[i].w + B[j].w, 0.f);
                    acc[i][j][0] += r * W1.z; acc[i][j][1] += r * W1.w;
                }
            }
        }
        __syncthreads();
    }

    // ---- 2-step tree reduction across the 4 h-groups (alias over sm) ----
    float (*red)[64][12] = reinterpret_cast<float (*)[64][12]>(sm);
    float* af = (float*)acc;                // 8 floats
    // 4 -> 2
    if (g >= 2) {
        *(float4*)&red[g - 2][lt][0] = *(const float4*)&af[0];
        *(float4*)&red[g - 2][lt][4] = *(const float4*)&af[4];
    }
    __syncthreads();
    if (g < 2) {
        #pragma unroll
        for (int k = 0; k < 8; k++) af[k] += red[g][lt][k];
    }
    __syncthreads();
    // 2 -> 1
    if (g == 1) {
        *(float4*)&red[0][lt][0] = *(const float4*)&af[0];
        *(float4*)&red[0][lt][4] = *(const float4*)&af[4];
    }
    __syncthreads();
    if (g == 0) {
        const float c0 = b2[0], c1 = b2[1];
        #pragma unroll
        for (int i = 0; i < 2; i++) {
            #pragma unroll
            for (int j = 0; j < 2; j++) {
                int k0i = (i * 2 + j) * 2;
                float v0 = acc[i][j][0] + red[0][lt][k0i]     + c0;
                float v1 = acc[i][j][1] + red[0][lt][k0i + 1] + c1;
                int s = st * 16 + sq + 8 * i;
                int t = tt * 16 + tq + 8 * j;
                *(float2*)&out[(((size_t)batch * SEQ + s) * SEQ + t) * NOUT]
                    = make_float2(v0, v1);
            }
        }
    }
}

// ---------------------------------------------------------------------------
extern "C" void kernel_launch(void* const* d_in, const int* in_sizes, int n_in,
                              void* d_out, int out_size)
{
    const float* a  = (const float*)d_in[0];
    const float* b  = (const float*)d_in[1];
    const float* W1 = (const float*)d_in[2];
    const float* b1 = (const float*)d_in[3];
    const float* W2 = (const float*)d_in[4];
    const float* b2 = (const float*)d_in[5];
    float* out = (float*)d_out;

    cudaFuncSetAttribute(proj_tc, cudaFuncAttributeMaxDynamicSharedMemorySize,
                         PROJ_SMEM_BYTES);

    // zero the RED targets (graph-capturable memset nodes, no allocation)
    void* pha = nullptr; void* phb = nullptr;
    cudaGetSymbolAddress(&pha, g_ha);
    cudaGetSymbolAddress(&phb, g_hb);
    cudaMemsetAsync(pha, 0, MROWS * HID * sizeof(float), 0);
    cudaMemsetAsync(phb, 0, MROWS * HID * sizeof(float), 0);

    proj_tc<<<dim3(HID / 64, MROWS / 64, 4), 128, PROJ_SMEM_BYTES>>>(a, b, W1, b1);
    pair_kernel<<<dim3(SEQ / 16, SEQ / 16, BS), 256>>>(W2, b2, out);
}

// round 14
// speedup vs baseline: 1.0760x; 1.0760x over previous
#include <cuda_runtime.h>
#include <cstdint>

#define BS   4
#define SEQ  128
#define DIM  768
#define HID  768
#define NOUT 2
#define MROWS (BS * SEQ)                    // 512
#define KSPLIT 384                          // K per split-K half

typedef unsigned long long u64;

// ---------------- device scratch (no allocation allowed) -------------------
__device__ float g_ha[MROWS * HID];         // partial: a @ W1[:D], k-half 0
__device__ float g_hb[MROWS * HID];         // partial: b @ W1[D:] + b1, k-half 0
__device__ float g_ha2[MROWS * HID];        // partial k-half 1
__device__ float g_hb2[MROWS * HID];        // partial k-half 1

// ---------------------------------------------------------------------------
__device__ __forceinline__ uint32_t smem_u32(const void* p) {
    uint32_t a;
    asm("{ .reg .u64 t; cvta.to.shared.u64 t, %1; cvt.u32.u64 %0, t; }"
        : "=r"(a) : "l"(p));
    return a;
}

__device__ __forceinline__ void cp_async16(uint32_t saddr, const void* gptr) {
    asm volatile("cp.async.cg.shared.global [%0], [%1], 16;"
                 :: "r"(saddr), "l"(gptr) : "memory");
}
__device__ __forceinline__ void cp_commit() {
    asm volatile("cp.async.commit_group;" ::: "memory");
}
template <int N>
__device__ __forceinline__ void cp_wait() {
    asm volatile("cp.async.wait_group %0;" :: "n"(N) : "memory");
}

__device__ __forceinline__ uint32_t f2tf32(float x) {
    uint32_t u;
    asm("cvt.rna.tf32.f32 %0, %1;" : "=r"(u) : "f"(x));
    return u;
}

__device__ __forceinline__ void ldsm_x4(uint32_t* d, uint32_t saddr) {
    asm volatile(
        "ldmatrix.sync.aligned.m8n8.x4.shared.b16 {%0,%1,%2,%3}, [%4];"
        : "=r"(d[0]), "=r"(d[1]), "=r"(d[2]), "=r"(d[3]) : "r"(saddr));
}

__device__ __forceinline__ void mma_tf32(float* c, const uint32_t* a,
                                         const uint32_t* b) {
    asm volatile(
        "mma.sync.aligned.m16n8k8.row.col.f32.tf32.tf32.f32 "
        "{%0,%1,%2,%3}, {%4,%5,%6,%7}, {%8,%9}, {%0,%1,%2,%3};"
        : "+f"(c[0]), "+f"(c[1]), "+f"(c[2]), "+f"(c[3])
        : "r"(a[0]), "r"(a[1]), "r"(a[2]), "r"(a[3]), "r"(b[0]), "r"(b[1]));
}

// ---- packed f32x2 helpers -------------------------------------------------
__device__ __forceinline__ u64 pack2(float lo, float hi) {
    u64 r;
    asm("mov.b64 %0, {%1, %2};" : "=l"(r) : "f"(lo), "f"(hi));
    return r;
}
__device__ __forceinline__ void unpack2(float& lo, float& hi, u64 v) {
    asm("mov.b64 {%0, %1}, %2;" : "=f"(lo), "=f"(hi) : "l"(v));
}
__device__ __forceinline__ u64 add2(u64 a, u64 b) {
    u64 r;
    asm("add.rn.f32x2 %0, %1, %2;" : "=l"(r) : "l"(a), "l"(b));
    return r;
}
__device__ __forceinline__ u64 fma2(u64 a, u64 b, u64 c) {
    u64 r;
    asm("fma.rn.f32x2 %0, %1, %2, %3;" : "=l"(r) : "l"(a), "l"(b), "l"(c));
    return r;
}

// ---------------------------------------------------------------------------
// Kernel 1: projection GEMM (R12 — proven). Split-K=2 into separate buffers.
// ---------------------------------------------------------------------------
#define ALD 36
#define BLD 72
#define STG_A (64 * ALD)
#define STG_B (32 * BLD)
#define PROJ_SMEM_BYTES (3 * (STG_A + STG_B) * 4)   // 55296

__global__ __launch_bounds__(128) void proj_tc(
    const float* __restrict__ a, const float* __restrict__ b,
    const float* __restrict__ W1, const float* __restrict__ b1)
{
    extern __shared__ float psm[];
    float* const Asm = psm;
    float* const Bsm = psm + 3 * STG_A;

    const int tid = threadIdx.x;
    const int wid = tid >> 5;
    const int lane = tid & 31;
    const int r = lane >> 2;
    const int c = lane & 3;
    const int wm = (wid >> 1) * 32;
    const int wn = (wid & 1) * 32;

    const int n0 = blockIdx.x * 64;
    const int m0 = blockIdx.y * 64;
    const int z  = blockIdx.z & 1;
    const int kh = blockIdx.z >> 1;
    const int kbase = kh * KSPLIT;

    const float* __restrict__ X = z ? b : a;
    const float* __restrict__ W = W1 + (size_t)z * DIM * HID;

    const uint32_t sA = smem_u32(Asm);
    const uint32_t sB = smem_u32(Bsm);

    const uint32_t a_lm0 =
        (uint32_t)(((wm + (lane & 7) + ((lane >> 3) & 1) * 8) * ALD
                    + ((lane >> 4) & 1) * 4) * 4);

    auto ldchunk = [&](int chunk, int s) {
        const int k0 = kbase + chunk * 32;
        #pragma unroll
        for (int i = 0; i < 4; i++) {
            int f = i * 128 + tid;
            int row = f >> 3, kc = (f & 7) * 4;
            cp_async16(sA + (uint32_t)(s * STG_A + row * ALD + kc) * 4,
                       X + (size_t)(m0 + row) * DIM + k0 + kc);
        }
        #pragma unroll
        for (int i = 0; i < 4; i++) {
            int f = i * 128 + tid;
            int kr = f >> 4, nc = (f & 15) * 4;
            cp_async16(sB + (uint32_t)(s * STG_B + kr * BLD + nc) * 4,
                       W + (size_t)(k0 + kr) * HID + n0 + nc);
        }
        cp_commit();
    };

    float acc[2][4][4] = {};

    ldchunk(0, 0);
    ldchunk(1, 1);

    for (int chunk = 0; chunk < 12; chunk++) {
        const int s = chunk % 3;
        if (chunk < 11) cp_wait<1>(); else cp_wait<0>();
        __syncthreads();

        if (chunk + 2 < 12) ldchunk(chunk + 2, (chunk + 2) % 3);

        const uint32_t aStage = sA + (uint32_t)(s * STG_A) * 4;
        const float* Bb = Bsm + s * STG_B;
        #pragma unroll
        for (int ks = 0; ks < 4; ks++) {
            const int kb = ks * 8;
            uint32_t af[2][4];
            #pragma unroll
            for (int mt = 0; mt < 2; mt++) {
                ldsm_x4(af[mt], aStage + a_lm0
                                + (uint32_t)(mt * 16 * ALD + kb) * 4);
                af[mt][0] = f2tf32(__uint_as_float(af[mt][0]));
                af[mt][1] = f2tf32(__uint_as_float(af[mt][1]));
                af[mt][2] = f2tf32(__uint_as_float(af[mt][2]));
                af[mt][3] = f2tf32(__uint_as_float(af[mt][3]));
            }
            uint32_t bf[4][2];
            #pragma unroll
            for (int nt = 0; nt < 4; nt++) {
                const float* bp = Bb + (kb + c) * BLD + wn + nt * 8 + r;
                bf[nt][0] = f2tf32(bp[0]);
                bf[nt][1] = f2tf32(bp[4 * BLD]);
            }
            #pragma unroll
            for (int nt = 0; nt < 4; nt++)
                #pragma unroll
                for (int mt = 0; mt < 2; mt++)
                    mma_tf32(acc[mt][nt], af[mt], bf[nt]);
        }
    }

    float* __restrict__ outp = z ? (kh ? g_hb2 : g_hb) : (kh ? g_ha2 : g_ha);
    const bool addb = (z == 1) && (kh == 0);
    #pragma unroll
    for (int mt = 0; mt < 2; mt++) {
        #pragma unroll
        for (int nt = 0; nt < 4; nt++) {
            int m = m0 + wm + mt * 16 + r;
            int n = n0 + wn + nt * 8 + c * 2;
            float2 v0 = make_float2(acc[mt][nt][0], acc[mt][nt][1]);
            float2 v1 = make_float2(acc[mt][nt][2], acc[mt][nt][3]);
            if (addb) {
                float2 bb = *(const float2*)&b1[n];
                v0.x += bb.x; v0.y += bb.y;
                v1.x += bb.x; v1.y += bb.y;
            }
            *(float2*)&outp[(size_t)m * HID + n] = v0;
            *(float2*)&outp[(size_t)(m + 8) * HID + n] = v1;
        }
    }
}

// ---------------------------------------------------------------------------
// Kernel 2: pairwise relu + reduce — packed f32x2 inner loop.
// Tile 16s x 16t, grid (8, 8, 4) = 256 CTAs, 256 threads.
// 4 h-groups of 64 threads (192 h each, 6 chunks of 32 h).
// Thread tile: 2 s (sq, sq+8) x 2 t packed (tq*2, tq*2+1).
// relu(x)*w computed exactly as (x+|x|)*(w/2); W2 pre-halved+duplicated in
// smem as u64 pairs; B stored transposed [h][t] so LDS.64 yields the t-pair.
// Per (s,h): 1 mov + 2 add2 + 2 fma2 -> fma-pipe 2 ops/element.
// ---------------------------------------------------------------------------
// per-group smem: sA 16x36=576 | sBT 32x18=576 | sW 32x4=128
#define QA_OFF(gg)  ((gg) * 576)
#define QB_OFF(gg)  (2304 + (gg) * 576)
#define QW_OFF(gg)  (4608 + (gg) * 128)
#define Q_SM_TOT    5120                     // floats (20480 B)

__global__ __launch_bounds__(256, 4) void pair_kernel(
    const float* __restrict__ W2, const float* __restrict__ b2,
    float* __restrict__ out)
{
    __shared__ float sm[Q_SM_TOT];

    const int tt = blockIdx.x;              // t tile (16)
    const int st = blockIdx.y;              // s tile (16)
    const int batch = blockIdx.z;

    const int tid = threadIdx.x;
    const int g  = tid >> 6;                // 0..3 h-group
    const int lt = tid & 63;
    const int sq = lt >> 3;                 // 0..7
    const int tq = lt & 7;                  // 0..7

    float* const sA  = sm + QA_OFF(g);      // [16][36]  (s-major)
    float* const sBT = sm + QB_OFF(g);      // [32][18]  (h-major, transposed)
    float* const sW  = sm + QW_OFF(g);      // [32][4]   (w0/2,w0/2,w1/2,w1/2)

    const float* __restrict__ hap  = g_ha  + (size_t)(batch * SEQ + st * 16) * HID;
    const float* __restrict__ hap2 = g_ha2 + (size_t)(batch * SEQ + st * 16) * HID;
    const float* __restrict__ hbp  = g_hb  + (size_t)(batch * SEQ + tt * 16) * HID;
    const float* __restrict__ hbp2 = g_hb2 + (size_t)(batch * SEQ + tt * 16) * HID;

    const u64 ABSM = 0x7FFFFFFF7FFFFFFFull;
    u64 acc[2][2] = {};                     // [s][o], lanes = (t0, t1)

    #pragma unroll 1
    for (int c = 0; c < 6; c++) {
        const int h0 = g * 192 + c * 32;

        // A fill: 16 s x 32 h = 128 f4, 2 per thread (merge split-K)
        #pragma unroll
        for (int q = 0; q < 2; q++) {
            int f = q * 64 + lt;
            int row = f >> 3, col = (f & 7) * 4;
            float4 u  = *(const float4*)&hap [(size_t)row * HID + h0 + col];
            float4 u2 = *(const float4*)&hap2[(size_t)row * HID + h0 + col];
            u.x += u2.x; u.y += u2.y; u.z += u2.z; u.w += u2.w;
            *(float4*)&sA[row * 36 + col] = u;
        }
        // B fill (transposed): read [t][h] f4, scatter 4 scalars to [h][t]
        #pragma unroll
        for (int q = 0; q < 2; q++) {
            int f = q * 64 + lt;
            int row = f >> 3, col = (f & 7) * 4;         // row = t, col = h
            float4 v  = *(const float4*)&hbp [(size_t)row * HID + h0 + col];
            float4 v2 = *(const float4*)&hbp2[(size_t)row * HID + h0 + col];
            v.x += v2.x; v.y += v2.y; v.z += v2.z; v.w += v2.w;
            sBT[(col + 0) * 18 + row] = v.x;
            sBT[(col + 1) * 18 + row] = v.y;
            sBT[(col + 2) * 18 + row] = v.z;
            sBT[(col + 3) * 18 + row] = v.w;
        }
        // W fill: 32 h, duplicated + pre-halved
        if (lt < 32) {
            float2 w = *(const float2*)&W2[(h0 + lt) * 2];
            w.x *= 0.5f; w.y *= 0.5f;
            *(float4*)&sW[lt * 4] = make_float4(w.x, w.x, w.y, w.y);
        }
        __syncthreads();

        #pragma unroll
        for (int hh = 0; hh < 32; hh += 4) {
            float4 As0 = *(const float4*)&sA[sq * 36 + hh];
            float4 As1 = *(const float4*)&sA[(sq + 8) * 36 + hh];
            const float* a0 = &As0.x;
            const float* a1 = &As1.x;
            #pragma unroll
            for (int k = 0; k < 4; k++) {
                u64 bb = *(const u64*)&sBT[(hh + k) * 18 + tq * 2];
                ulonglong2 wp = *(const ulonglong2*)&sW[(hh + k) * 4];

                u64 aa0 = pack2(a0[k], a0[k]);
                u64 x0  = add2(aa0, bb);
                u64 s0  = add2(x0, x0 & ABSM);           // 2*relu
                acc[0][0] = fma2(s0, wp.x, acc[0][0]);
                acc[0][1] = fma2(s0, wp.y, acc[0][1]);

                u64 aa1 = pack2(a1[k], a1[k]);
                u64 x1  = add2(aa1, bb);
                u64 s1  = add2(x1, x1 & ABSM);
                acc[1][0] = fma2(s1, wp.x, acc[1][0]);
                acc[1][1] = fma2(s1, wp.y, acc[1][1]);
            }
        }
        __syncthreads();
    }

    // unpack accumulators: af[(i*2+j)*2+o], j = t lane
    float af[8];
    #pragma unroll
    for (int i = 0; i < 2; i++) {
        #pragma unroll
        for (int o = 0; o < 2; o++) {
            float t0v, t1v;
            unpack2(t0v, t1v, acc[i][o]);
            af[(i * 2 + 0) * 2 + o] = t0v;
            af[(i * 2 + 1) * 2 + o] = t1v;
        }
    }

    // ---- 2-step tree reduction across the 4 h-groups (alias over sm) ----
    float (*red)[64][12] = reinterpret_cast<float (*)[64][12]>(sm);
    // 4 -> 2
    if (g >= 2) {
        *(float4*)&red[g - 2][lt][0] = *(const float4*)&af[0];
        *(float4*)&red[g - 2][lt][4] = *(const float4*)&af[4];
    }
    __syncthreads();
    if (g < 2) {
        #pragma unroll
        for (int k = 0; k < 8; k++) af[k] += red[g][lt][k];
    }
    __syncthreads();
    // 2 -> 1
    if (g == 1) {
        *(float4*)&red[0][lt][0] = *(const float4*)&af[0];
        *(float4*)&red[0][lt][4] = *(const float4*)&af[4];
    }
    __syncthreads();
    if (g == 0) {
        const float c0 = b2[0], c1 = b2[1];
        #pragma unroll
        for (int i = 0; i < 2; i++) {
            #pragma unroll
            for (int j = 0; j < 2; j++) {
                int k0i = (i * 2 + j) * 2;
                float v0 = af[k0i]     + red[0][lt][k0i]     + c0;
                float v1 = af[k0i + 1] + red[0][lt][k0i + 1] + c1;
                int s = st * 16 + sq + 8 * i;
                int t = tt * 16 + tq * 2 + j;
                *(float2*)&out[(((size_t)batch * SEQ + s) * SEQ + t) * NOUT]
                    = make_float2(v0, v1);
            }
        }
    }
}

// ---------------------------------------------------------------------------
extern "C" void kernel_launch(void* const* d_in, const int* in_sizes, int n_in,
                              void* d_out, int out_size)
{
    const float* a  = (const float*)d_in[0];
    const float* b  = (const float*)d_in[1];
    const float* W1 = (const float*)d_in[2];
    const float* b1 = (const float*)d_in[3];
    const float* W2 = (const float*)d_in[4];
    const float* b2 = (const float*)d_in[5];
    float* out = (float*)d_out;

    cudaFuncSetAttribute(proj_tc, cudaFuncAttributeMaxDynamicSharedMemorySize,
                         PROJ_SMEM_BYTES);

    proj_tc<<<dim3(HID / 64, MROWS / 64, 4), 128, PROJ_SMEM_BYTES>>>(a, b, W1, b1);
    pair_kernel<<<dim3(SEQ / 16, SEQ / 16, BS), 256>>>(W2, b2, out);
}